// round 13
// baseline (speedup 1.0000x reference)
#include <cuda_runtime.h>
#include <cuda_bf16.h>
#include <cuda_fp16.h>
#include <cstdint>
#include <math.h>

#define NB  4
#define NT  2048
#define NC  1024
#define NHH 16
#define HD  64
#define HP  32   // HD/2 packed u32 per row

// ---------------- device-global scratch (no cudaMalloc allowed) ----------------
// flash inputs: fp16 (Q single; K split; V^T split)
__device__ uint32_t g_q16 [(size_t)NB * NHH * NT * HP];
__device__ uint32_t g_k16h[(size_t)NB * NHH * NT * HP];
__device__ uint32_t g_k16l[(size_t)NB * NHH * NT * HP];
__device__ uint16_t g_vt16h[(size_t)NB * NHH * HD * NT];   // V^T fp16 [b,h][d][t]
__device__ uint16_t g_vt16l[(size_t)NB * NHH * HD * NT];
// GEMM inputs: fp16 (A single, B split)
__device__ uint32_t g_x16 [(size_t)NB * NT * (NC / 2)];
__device__ uint32_t g_wa16h[(size_t)3 * NC * (NC / 2)];
__device__ uint32_t g_wa16l[(size_t)3 * NC * (NC / 2)];
__device__ uint32_t g_wp16h[(size_t)NC * (NC / 2)];
__device__ uint32_t g_wp16l[(size_t)NC * (NC / 2)];
__device__ uint32_t g_y16 [(size_t)NB * NT * (NC / 2)];

// ============================ helpers ============================
__device__ __forceinline__ uint32_t pack_f16(float a, float b) {
    __half2 t = __floats2half2_rn(a, b);
    return *(uint32_t*)&t;
}
__device__ __forceinline__ void split2h(float x, float& hi, float& lo) {
    __half h = __float2half_rn(x);
    hi = __half2float(h);
    lo = x - hi;
}
__device__ __forceinline__ void mma_f16(float* d, const uint32_t* a, const uint32_t* b) {
    asm volatile(
        "mma.sync.aligned.m16n8k16.row.col.f32.f16.f16.f32 "
        "{%0,%1,%2,%3}, {%4,%5,%6,%7}, {%8,%9}, {%0,%1,%2,%3};"
        : "+f"(d[0]), "+f"(d[1]), "+f"(d[2]), "+f"(d[3])
        : "r"(a[0]), "r"(a[1]), "r"(a[2]), "r"(a[3]), "r"(b[0]), "r"(b[1]));
}
__device__ __forceinline__ uint32_t smem_u32(const void* p) {
    uint32_t a;
    asm("{ .reg .u64 t; cvta.to.shared.u64 t, %1; cvt.u32.u64 %0, t; }"
        : "=r"(a) : "l"(p));
    return a;
}
__device__ __forceinline__ void cp16(uint32_t dst, const void* src) {
    asm volatile("cp.async.cg.shared.global [%0], [%1], 16;" :: "r"(dst), "l"(src));
}
#define CP_COMMIT() asm volatile("cp.async.commit_group;" ::: "memory")
#define CP_WAIT1()  asm volatile("cp.async.wait_group 1;" ::: "memory")
#define CP_WAIT0()  asm volatile("cp.async.wait_group 0;" ::: "memory")

// ===================== pre-split kernels =====================
__global__ __launch_bounds__(256) void split_x16_kernel(
    const float* __restrict__ src, uint32_t* __restrict__ d16, int npairs)
{
    int i = blockIdx.x * 256 + threadIdx.x;
    if (i < npairs) {
        float2 v = ((const float2*)src)[i];
        d16[i] = pack_f16(v.x, v.y);
    }
}

template <int N>
__global__ __launch_bounds__(256) void split_wT16_kernel(
    const float* __restrict__ w, uint32_t* __restrict__ wth, uint32_t* __restrict__ wtl)
{
    __shared__ float ws[32][65];
    const int tid = threadIdx.x;
    const int n0 = blockIdx.x * 64, k0 = blockIdx.y * 32;
#pragma unroll
    for (int it = 0; it < 8; it++) {
        int s = tid + it * 256;
        int r = s >> 6, c = s & 63;
        ws[r][c] = w[(size_t)(k0 + r) * N + n0 + c];
    }
    __syncthreads();
#pragma unroll
    for (int it = 0; it < 4; it++) {
        int s = tid + it * 256;
        int n = s >> 4, kp = s & 15;
        float f0 = ws[2 * kp][n], f1 = ws[2 * kp + 1][n];
        float h0, l0, h1, l1;
        split2h(f0, h0, l0); split2h(f1, h1, l1);
        size_t o = (size_t)(n0 + n) * (NC / 2) + (k0 >> 1) + kp;
        wth[o] = pack_f16(h0, h1);
        wtl[o] = pack_f16(l0, l1);
    }
}

// ===================== fp16 2-pass GEMM: 2-stage cp.async, occupancy 2 =====================
static constexpr int BM = 128, BN = 128, BK = 32;
static constexpr int KTOT = 1024, NCHUNK = KTOT / BK, KP = KTOT / 2;
static constexpr int LDP = 20;
static constexpr int G_STG = 7680;
static constexpr int G_SMEM_BYTES = 2 * G_STG * 4;    // 61440 -> 2 CTAs/SM

template <int MODE>
__global__ __launch_bounds__(256, 2) void gemm_f16_kernel(
    const float* __restrict__ bias, float* __restrict__ out)
{
    extern __shared__ uint32_t dsm[];
    const uint32_t dsm_b = smem_u32(dsm);

    const int tid  = threadIdx.x;
    const int warp = tid >> 5, lane = tid & 31;
    const int g = lane >> 2, tq = lane & 3;
    const int wm = (warp >> 2) * 64;
    const int wn = (warp & 3) * 32;
    const int m0 = blockIdx.y * BM, n0 = blockIdx.x * BN;

    const uint32_t* __restrict__ Ax = (MODE == 0) ? g_x16 : g_y16;
    const uint32_t* __restrict__ Bh = (MODE == 0) ? g_wa16h : g_wp16h;
    const uint32_t* __restrict__ Bl = (MODE == 0) ? g_wa16l : g_wp16l;

    const int srow = tid >> 2, sq = (tid & 3) * 4;

    auto issue = [&](int ci) {
        const int kp0 = ci * (BK / 2);
        const uint32_t st = dsm_b + (ci & 1) * (G_STG * 4);
#pragma unroll
        for (int it = 0; it < 2; it++) {
            int row = srow + it * 64;
            uint32_t doff = (row * LDP + sq) * 4;
            cp16(st + doff, Ax + (size_t)(m0 + row) * KP + kp0 + sq);
            const size_t bsrc = (size_t)(n0 + row) * KP + kp0 + sq;
            cp16(st + 10240 + doff, Bh + bsrc);
            cp16(st + 20480 + doff, Bl + bsrc);
        }
    };

    float acc[4][4][4] = {};

    issue(0); CP_COMMIT();

    for (int ci = 0; ci < NCHUNK; ci++) {
        if (ci + 1 < NCHUNK) {
            issue(ci + 1); CP_COMMIT();
            CP_WAIT1();
        } else {
            CP_WAIT0();
        }
        __syncthreads();

        const uint32_t* st = dsm + (ci & 1) * G_STG;
        const uint32_t* As   = st;
        const uint32_t* Bs_h = st + 2560;
        const uint32_t* Bs_l = st + 5120;
#pragma unroll
        for (int ks = 0; ks < 2; ks++) {
            const int pb2 = ks * 8 + tq;
            uint32_t ah[4][4];
#pragma unroll
            for (int fm = 0; fm < 4; fm++) {
                int r0 = (wm + fm * 16 + g) * LDP + pb2;
                int r1 = r0 + 8 * LDP;
                ah[fm][0] = As[r0];     ah[fm][1] = As[r1];
                ah[fm][2] = As[r0 + 4]; ah[fm][3] = As[r1 + 4];
            }
            uint32_t bh[4][2], bl[4][2];
#pragma unroll
            for (int fn = 0; fn < 4; fn++) {
                int o = (wn + fn * 8 + g) * LDP + pb2;
                bh[fn][0] = Bs_h[o]; bh[fn][1] = Bs_h[o + 4];
                bl[fn][0] = Bs_l[o]; bl[fn][1] = Bs_l[o + 4];
            }
#pragma unroll
            for (int fm = 0; fm < 4; fm++)
#pragma unroll
                for (int fn = 0; fn < 4; fn++) {
                    mma_f16(acc[fm][fn], ah[fm], bl[fn]);
                    mma_f16(acc[fm][fn], ah[fm], bh[fn]);
                }
        }

        __syncthreads();
    }

    // ---- epilogue ----
#pragma unroll
    for (int fm = 0; fm < 4; fm++) {
#pragma unroll
        for (int fn = 0; fn < 4; fn++) {
            int ng = n0 + wn + fn * 8 + tq * 2;
#pragma unroll
            for (int half = 0; half < 2; half++) {
                int m = m0 + wm + fm * 16 + g + half * 8;
                float v0 = acc[fm][fn][half * 2 + 0] + bias[ng];
                float v1 = acc[fm][fn][half * 2 + 1] + bias[ng + 1];
                if (MODE == 0) {
                    const int which = ng >> 10;
                    const int h = (ng & (NC - 1)) >> 6;
                    const int d = ng & (HD - 1);
                    const int b = m >> 11, t = m & (NT - 1);
                    if (which == 0) {
                        // Q: single fp16
                        size_t idx = (((size_t)b * NHH + h) * NT + t) * HP + (d >> 1);
                        g_q16[idx] = pack_f16(v0, v1);
                    } else if (which == 1) {
                        // K: split fp16
                        float h0, l0, h1, l1;
                        split2h(v0, h0, l0); split2h(v1, h1, l1);
                        size_t idx = (((size_t)b * NHH + h) * NT + t) * HP + (d >> 1);
                        g_k16h[idx] = pack_f16(h0, h1);
                        g_k16l[idx] = pack_f16(l0, l1);
                    } else {
                        // V: split fp16, transposed [b,h][d][t]
                        float h0, l0, h1, l1;
                        split2h(v0, h0, l0); split2h(v1, h1, l1);
                        size_t vb = ((size_t)(b * NHH + h) * HD + d) * NT + t;
                        uint32_t ph = pack_f16(h0, h1), pl = pack_f16(l0, l1);
                        g_vt16h[vb]      = (uint16_t)(ph & 0xffff);
                        g_vt16h[vb + NT] = (uint16_t)(ph >> 16);
                        g_vt16l[vb]      = (uint16_t)(pl & 0xffff);
                        g_vt16l[vb + NT] = (uint16_t)(pl >> 16);
                    }
                } else {
                    *(float2*)(out + (size_t)m * NC + ng) = make_float2(v0, v1);
                }
            }
        }
    }
}

// ===================== flash attention: fp16 2-pass, cp.async, occ 2 =====================
static constexpr int FP = 36;
// stage layout (u32): Ksh 0 | Ksl 2304 | Vth 4608 | Vtl 6912
static constexpr int F_STG = 9216;
static constexpr int F_SMEM_BYTES = 2 * F_STG * 4;    // 73728

__global__ __launch_bounds__(256, 2) void flash_mma_kernel()
{
    extern __shared__ uint32_t fsm[];
    const uint32_t fsm_b = smem_u32(fsm);

    const int tid  = threadIdx.x;
    const int warp = tid >> 5, lane = tid & 31;
    const int g = lane >> 2, tq = lane & 3;
    const int qi = blockIdx.x, bh = blockIdx.y;
    const int q0 = qi * 128;
    const int rw = q0 + warp * 16 + g;

    const size_t base = (size_t)bh * NT * HP;
    const uint32_t* __restrict__ q16 = g_q16 + base;
    const uint32_t* __restrict__ kh  = g_k16h + base;
    const uint32_t* __restrict__ kl  = g_k16l + base;
    const uint32_t* __restrict__ vth32 = (const uint32_t*)(const void*)g_vt16h
                                         + (size_t)bh * HD * (NT / 2);
    const uint32_t* __restrict__ vtl32 = (const uint32_t*)(const void*)g_vt16l
                                         + (size_t)bh * HD * (NT / 2);

    auto issue = [&](int kt) {
        const uint32_t st = fsm_b + (kt & 1) * (F_STG * 4);
#pragma unroll
        for (int it = 0; it < 2; it++) {
            int c = tid + it * 256;
            int row = c >> 3, pr = (c & 7) * 4;
            uint32_t doff = (row * FP + pr) * 4;
            const size_t ksrc = (size_t)(kt * 64 + row) * HP + pr;
            cp16(st + doff,         kh + ksrc);
            cp16(st + 9216 + doff,  kl + ksrc);
            const size_t vsrc = (size_t)row * (NT / 2) + (size_t)kt * 32 + pr;
            cp16(st + 18432 + doff, vth32 + vsrc);
            cp16(st + 27648 + doff, vtl32 + vsrc);
        }
    };

    // Q fragments (single fp16; rows rw, rw+8; full HD)
    uint32_t qa[4][4];
#pragma unroll
    for (int s = 0; s < 4; s++) {
        int o0 = rw * HP + s * 8 + tq;
        int o1 = (rw + 8) * HP + s * 8 + tq;
        qa[s][0] = q16[o0]; qa[s][1] = q16[o1];
        qa[s][2] = q16[o0 + 4]; qa[s][3] = q16[o1 + 4];
    }

    float m_i[2] = {-1e30f, -1e30f}, l_i[2] = {0.f, 0.f};
    float o[8][4] = {};

    const int nkt = 2 * qi + 2;
    issue(0); CP_COMMIT();

    for (int kt = 0; kt < nkt; kt++) {
        if (kt + 1 < nkt) {
            issue(kt + 1); CP_COMMIT();
            CP_WAIT1();
        } else {
            CP_WAIT0();
        }
        __syncthreads();

        if (q0 + warp * 16 + 15 >= kt * 64) {
            uint32_t* st = fsm + (kt & 1) * F_STG;
            const uint32_t* Ksh = st;
            const uint32_t* Ksl = st + 2304;
            const uint32_t* Vth = st + 4608;
            const uint32_t* Vtl = st + 6912;

            // ---- S = Q K^T : fp16 2-pass ----
            float s[8][4];
#pragma unroll
            for (int nt = 0; nt < 8; nt++) {
                float sa[4] = {};
#pragma unroll
                for (int ks = 0; ks < 4; ks++) {
                    int ob = (nt * 8 + g) * FP + ks * 8 + tq;
                    uint32_t bh2[2] = {Ksh[ob], Ksh[ob + 4]};
                    uint32_t bl2[2] = {Ksl[ob], Ksl[ob + 4]};
                    mma_f16(sa, qa[ks], bl2);
                    mma_f16(sa, qa[ks], bh2);
                }
                s[nt][0] = sa[0]; s[nt][1] = sa[1]; s[nt][2] = sa[2]; s[nt][3] = sa[3];
            }

            const bool need_mask = (kt >= 2 * qi);
#pragma unroll
            for (int nt = 0; nt < 8; nt++) {
                int c0 = kt * 64 + nt * 8 + 2 * tq;
#pragma unroll
                for (int r = 0; r < 4; r++) {
                    int col = c0 + (r & 1);
                    int row = rw + (r >> 1) * 8;
                    float v = s[nt][r] * 0.125f;
                    if (need_mask && col > row) v = -1e30f;
                    s[nt][r] = v;
                }
            }

            float sc[2];
#pragma unroll
            for (int r = 0; r < 2; r++) {
                float mx = -1e30f;
#pragma unroll
                for (int nt = 0; nt < 8; nt++)
                    mx = fmaxf(mx, fmaxf(s[nt][2 * r], s[nt][2 * r + 1]));
                mx = fmaxf(mx, __shfl_xor_sync(0xffffffffu, mx, 1));
                mx = fmaxf(mx, __shfl_xor_sync(0xffffffffu, mx, 2));
                float m_new = fmaxf(m_i[r], mx);
                float sum = 0.f;
#pragma unroll
                for (int nt = 0; nt < 8; nt++) {
                    float p0 = __expf(s[nt][2 * r] - m_new);
                    float p1 = __expf(s[nt][2 * r + 1] - m_new);
                    s[nt][2 * r] = p0; s[nt][2 * r + 1] = p1;
                    sum += p0 + p1;
                }
                sum += __shfl_xor_sync(0xffffffffu, sum, 1);
                sum += __shfl_xor_sync(0xffffffffu, sum, 2);
                sc[r]  = __expf(m_i[r] - m_new);
                l_i[r] = l_i[r] * sc[r] + sum;
                m_i[r] = m_new;
            }
#pragma unroll
            for (int nt = 0; nt < 8; nt++) {
                o[nt][0] *= sc[0]; o[nt][1] *= sc[0];
                o[nt][2] *= sc[1]; o[nt][3] *= sc[1];
            }

            // ---- PV: P single fp16, V split 2-pass ----
#pragma unroll
            for (int ks = 0; ks < 4; ks++) {
                uint32_t pa[4] = {
                    pack_f16(s[2 * ks][0],     s[2 * ks][1]),
                    pack_f16(s[2 * ks][2],     s[2 * ks][3]),
                    pack_f16(s[2 * ks + 1][0], s[2 * ks + 1][1]),
                    pack_f16(s[2 * ks + 1][2], s[2 * ks + 1][3])
                };
#pragma unroll
                for (int nt = 0; nt < 8; nt++) {
                    int ob = (nt * 8 + g) * FP + ks * 8 + tq;
                    uint32_t bh2[2] = {Vth[ob], Vth[ob + 4]};
                    uint32_t bl2[2] = {Vtl[ob], Vtl[ob + 4]};
                    mma_f16(o[nt], pa, bl2);
                    mma_f16(o[nt], pa, bh2);
                }
            }
        }

        __syncthreads();
    }

    // ---- epilogue: write y as fp16x2 ----
    const int b = bh >> 4, h = bh & 15;
    float inv0 = 1.f / l_i[0], inv1 = 1.f / l_i[1];
#pragma unroll
    for (int nt = 0; nt < 8; nt++) {
        int dp = h * HP + nt * 4 + tq;
        g_y16[(size_t)(b * NT + rw) * (NC / 2) + dp] =
            pack_f16(o[nt][0] * inv0, o[nt][1] * inv0);
        g_y16[(size_t)(b * NT + rw + 8) * (NC / 2) + dp] =
            pack_f16(o[nt][2] * inv1, o[nt][3] * inv1);
    }
}

// ===========================================================================
extern "C" void kernel_launch(void* const* d_in, const int* in_sizes, int n_in,
                              void* d_out, int out_size)
{
    const float* x      = (const float*)d_in[0];
    const float* w_attn = (const float*)d_in[1];
    const float* b_attn = (const float*)d_in[2];
    const float* w_proj = (const float*)d_in[3];
    const float* b_proj = (const float*)d_in[4];
    float* out = (float*)d_out;

    cudaFuncSetAttribute(gemm_f16_kernel<0>,
                         cudaFuncAttributeMaxDynamicSharedMemorySize, G_SMEM_BYTES);
    cudaFuncSetAttribute(gemm_f16_kernel<1>,
                         cudaFuncAttributeMaxDynamicSharedMemorySize, G_SMEM_BYTES);
    cudaFuncSetAttribute(flash_mma_kernel,
                         cudaFuncAttributeMaxDynamicSharedMemorySize, F_SMEM_BYTES);

    // pre-split passes
    {
        uint32_t *x16, *wah, *wal, *wph, *wpl;
        cudaGetSymbolAddress((void**)&x16, g_x16);
        cudaGetSymbolAddress((void**)&wah, g_wa16h);
        cudaGetSymbolAddress((void**)&wal, g_wa16l);
        cudaGetSymbolAddress((void**)&wph, g_wp16h);
        cudaGetSymbolAddress((void**)&wpl, g_wp16l);
        const int npx = NB * NT * NC / 2;
        split_x16_kernel<<<(npx + 255) / 256, 256>>>(x, x16, npx);
        split_wT16_kernel<3 * NC><<<dim3(3 * NC / 64, NC / 32), 256>>>(w_attn, wah, wal);
        split_wT16_kernel<NC><<<dim3(NC / 64, NC / 32), 256>>>(w_proj, wph, wpl);
    }

    dim3 g1(3 * NC / BN, (NB * NT) / BM);   // (24, 64)
    gemm_f16_kernel<0><<<g1, 256, G_SMEM_BYTES>>>(b_attn, nullptr);

    dim3 g2(NT / 128, NB * NHH);            // (16, 64)
    flash_mma_kernel<<<g2, 256, F_SMEM_BYTES>>>();

    dim3 g3(NC / BN, (NB * NT) / BM);       // (8, 64)
    gemm_f16_kernel<1><<<g3, 256, G_SMEM_BYTES>>>(b_proj, out);
}

// round 14
// speedup vs baseline: 1.5503x; 1.5503x over previous
#include <cuda_runtime.h>
#include <cuda_bf16.h>
#include <cuda_fp16.h>
#include <cstdint>
#include <math.h>

#define NB  4
#define NT  2048
#define NC  1024
#define NHH 16
#define HD  64
#define HP  32   // HD/2 packed u32 per row

// ---------------- device-global scratch (no cudaMalloc allowed) ----------------
// flash inputs: fp16 (Q single; K split; V^T split)
__device__ uint32_t g_q16 [(size_t)NB * NHH * NT * HP];
__device__ uint32_t g_k16h[(size_t)NB * NHH * NT * HP];
__device__ uint32_t g_k16l[(size_t)NB * NHH * NT * HP];
__device__ uint16_t g_vt16h[(size_t)NB * NHH * HD * NT];   // V^T fp16 [b,h][d][t]
__device__ uint16_t g_vt16l[(size_t)NB * NHH * HD * NT];
// GEMM inputs: fp16 (A single, B split)
__device__ uint32_t g_x16 [(size_t)NB * NT * (NC / 2)];
__device__ uint32_t g_wa16h[(size_t)3 * NC * (NC / 2)];
__device__ uint32_t g_wa16l[(size_t)3 * NC * (NC / 2)];
__device__ uint32_t g_wp16h[(size_t)NC * (NC / 2)];
__device__ uint32_t g_wp16l[(size_t)NC * (NC / 2)];
__device__ uint32_t g_y16 [(size_t)NB * NT * (NC / 2)];

// ============================ helpers ============================
__device__ __forceinline__ uint32_t pack_f16(float a, float b) {
    __half2 t = __floats2half2_rn(a, b);
    return *(uint32_t*)&t;
}
__device__ __forceinline__ void split2h(float x, float& hi, float& lo) {
    __half h = __float2half_rn(x);
    hi = __half2float(h);
    lo = x - hi;
}
__device__ __forceinline__ void mma_f16(float* d, const uint32_t* a, const uint32_t* b) {
    asm volatile(
        "mma.sync.aligned.m16n8k16.row.col.f32.f16.f16.f32 "
        "{%0,%1,%2,%3}, {%4,%5,%6,%7}, {%8,%9}, {%0,%1,%2,%3};"
        : "+f"(d[0]), "+f"(d[1]), "+f"(d[2]), "+f"(d[3])
        : "r"(a[0]), "r"(a[1]), "r"(a[2]), "r"(a[3]), "r"(b[0]), "r"(b[1]));
}
__device__ __forceinline__ uint32_t smem_u32(const void* p) {
    uint32_t a;
    asm("{ .reg .u64 t; cvta.to.shared.u64 t, %1; cvt.u32.u64 %0, t; }"
        : "=r"(a) : "l"(p));
    return a;
}
__device__ __forceinline__ void cp16(uint32_t dst, const void* src) {
    asm volatile("cp.async.cg.shared.global [%0], [%1], 16;" :: "r"(dst), "l"(src));
}
#define CP_COMMIT() asm volatile("cp.async.commit_group;" ::: "memory")
#define CP_WAIT1()  asm volatile("cp.async.wait_group 1;" ::: "memory")
#define CP_WAIT0()  asm volatile("cp.async.wait_group 0;" ::: "memory")

// ===================== pre-split kernels =====================
__global__ __launch_bounds__(256) void split_x16_kernel(
    const float* __restrict__ src, uint32_t* __restrict__ d16, int npairs)
{
    int i = blockIdx.x * 256 + threadIdx.x;
    if (i < npairs) {
        float2 v = ((const float2*)src)[i];
        d16[i] = pack_f16(v.x, v.y);
    }
}

template <int N>
__global__ __launch_bounds__(256) void split_wT16_kernel(
    const float* __restrict__ w, uint32_t* __restrict__ wth, uint32_t* __restrict__ wtl)
{
    __shared__ float ws[32][65];
    const int tid = threadIdx.x;
    const int n0 = blockIdx.x * 64, k0 = blockIdx.y * 32;
#pragma unroll
    for (int it = 0; it < 8; it++) {
        int s = tid + it * 256;
        int r = s >> 6, c = s & 63;
        ws[r][c] = w[(size_t)(k0 + r) * N + n0 + c];
    }
    __syncthreads();
#pragma unroll
    for (int it = 0; it < 4; it++) {
        int s = tid + it * 256;
        int n = s >> 4, kp = s & 15;
        float f0 = ws[2 * kp][n], f1 = ws[2 * kp + 1][n];
        float h0, l0, h1, l1;
        split2h(f0, h0, l0); split2h(f1, h1, l1);
        size_t o = (size_t)(n0 + n) * (NC / 2) + (k0 >> 1) + kp;
        wth[o] = pack_f16(h0, h1);
        wtl[o] = pack_f16(l0, l1);
    }
}

// ===================== fp16 2-pass GEMM: 2-stage cp.async, occupancy 2 =====================
static constexpr int BM = 128, BN = 128, BK = 32;
static constexpr int KTOT = 1024, NCHUNK = KTOT / BK, KP = KTOT / 2;
static constexpr int LDP = 20;
static constexpr int G_STG = 7680;
static constexpr int G_SMEM_BYTES = 2 * G_STG * 4;    // 61440 -> 2 CTAs/SM

template <int MODE>
__global__ __launch_bounds__(256, 2) void gemm_f16_kernel(
    const float* __restrict__ bias, float* __restrict__ out)
{
    extern __shared__ uint32_t dsm[];
    const uint32_t dsm_b = smem_u32(dsm);

    const int tid  = threadIdx.x;
    const int warp = tid >> 5, lane = tid & 31;
    const int g = lane >> 2, tq = lane & 3;
    const int wm = (warp >> 2) * 64;
    const int wn = (warp & 3) * 32;
    const int m0 = blockIdx.y * BM, n0 = blockIdx.x * BN;

    const uint32_t* __restrict__ Ax = (MODE == 0) ? g_x16 : g_y16;
    const uint32_t* __restrict__ Bh = (MODE == 0) ? g_wa16h : g_wp16h;
    const uint32_t* __restrict__ Bl = (MODE == 0) ? g_wa16l : g_wp16l;

    const int srow = tid >> 2, sq = (tid & 3) * 4;

    auto issue = [&](int ci) {
        const int kp0 = ci * (BK / 2);
        const uint32_t st = dsm_b + (ci & 1) * (G_STG * 4);
#pragma unroll
        for (int it = 0; it < 2; it++) {
            int row = srow + it * 64;
            uint32_t doff = (row * LDP + sq) * 4;
            cp16(st + doff, Ax + (size_t)(m0 + row) * KP + kp0 + sq);
            const size_t bsrc = (size_t)(n0 + row) * KP + kp0 + sq;
            cp16(st + 10240 + doff, Bh + bsrc);
            cp16(st + 20480 + doff, Bl + bsrc);
        }
    };

    float acc[4][4][4] = {};

    issue(0); CP_COMMIT();

    for (int ci = 0; ci < NCHUNK; ci++) {
        if (ci + 1 < NCHUNK) {
            issue(ci + 1); CP_COMMIT();
            CP_WAIT1();
        } else {
            CP_WAIT0();
        }
        __syncthreads();

        const uint32_t* st = dsm + (ci & 1) * G_STG;
        const uint32_t* As   = st;
        const uint32_t* Bs_h = st + 2560;
        const uint32_t* Bs_l = st + 5120;
#pragma unroll
        for (int ks = 0; ks < 2; ks++) {
            const int pb2 = ks * 8 + tq;
            uint32_t ah[4][4];
#pragma unroll
            for (int fm = 0; fm < 4; fm++) {
                int r0 = (wm + fm * 16 + g) * LDP + pb2;
                int r1 = r0 + 8 * LDP;
                ah[fm][0] = As[r0];     ah[fm][1] = As[r1];
                ah[fm][2] = As[r0 + 4]; ah[fm][3] = As[r1 + 4];
            }
            uint32_t bh[4][2], bl[4][2];
#pragma unroll
            for (int fn = 0; fn < 4; fn++) {
                int o = (wn + fn * 8 + g) * LDP + pb2;
                bh[fn][0] = Bs_h[o]; bh[fn][1] = Bs_h[o + 4];
                bl[fn][0] = Bs_l[o]; bl[fn][1] = Bs_l[o + 4];
            }
#pragma unroll
            for (int fm = 0; fm < 4; fm++)
#pragma unroll
                for (int fn = 0; fn < 4; fn++) {
                    mma_f16(acc[fm][fn], ah[fm], bl[fn]);
                    mma_f16(acc[fm][fn], ah[fm], bh[fn]);
                }
        }

        __syncthreads();
    }

    // ---- epilogue ----
#pragma unroll
    for (int fm = 0; fm < 4; fm++) {
#pragma unroll
        for (int fn = 0; fn < 4; fn++) {
            int ng = n0 + wn + fn * 8 + tq * 2;
#pragma unroll
            for (int half = 0; half < 2; half++) {
                int m = m0 + wm + fm * 16 + g + half * 8;
                float v0 = acc[fm][fn][half * 2 + 0] + bias[ng];
                float v1 = acc[fm][fn][half * 2 + 1] + bias[ng + 1];
                if (MODE == 0) {
                    const int which = ng >> 10;
                    const int h = (ng & (NC - 1)) >> 6;
                    const int d = ng & (HD - 1);
                    const int b = m >> 11, t = m & (NT - 1);
                    if (which == 0) {
                        size_t idx = (((size_t)b * NHH + h) * NT + t) * HP + (d >> 1);
                        g_q16[idx] = pack_f16(v0, v1);
                    } else if (which == 1) {
                        float h0, l0, h1, l1;
                        split2h(v0, h0, l0); split2h(v1, h1, l1);
                        size_t idx = (((size_t)b * NHH + h) * NT + t) * HP + (d >> 1);
                        g_k16h[idx] = pack_f16(h0, h1);
                        g_k16l[idx] = pack_f16(l0, l1);
                    } else {
                        float h0, l0, h1, l1;
                        split2h(v0, h0, l0); split2h(v1, h1, l1);
                        size_t vb = ((size_t)(b * NHH + h) * HD + d) * NT + t;
                        uint32_t ph = pack_f16(h0, h1), pl = pack_f16(l0, l1);
                        g_vt16h[vb]      = (uint16_t)(ph & 0xffff);
                        g_vt16h[vb + NT] = (uint16_t)(ph >> 16);
                        g_vt16l[vb]      = (uint16_t)(pl & 0xffff);
                        g_vt16l[vb + NT] = (uint16_t)(pl >> 16);
                    }
                } else {
                    *(float2*)(out + (size_t)m * NC + ng) = make_float2(v0, v1);
                }
            }
        }
    }
}

// ===================== flash attention: fp16 2-pass, cp.async, occ 2 =====================
static constexpr int FP = 36;
static constexpr int F_STG = 9216;
static constexpr int F_SMEM_BYTES = 2 * F_STG * 4;    // 73728

__global__ __launch_bounds__(256, 2) void flash_mma_kernel()
{
    extern __shared__ uint32_t fsm[];
    const uint32_t fsm_b = smem_u32(fsm);

    const int tid  = threadIdx.x;
    const int warp = tid >> 5, lane = tid & 31;
    const int g = lane >> 2, tq = lane & 3;
    const int qi = blockIdx.x, bh = blockIdx.y;
    const int q0 = qi * 128;
    const int rw = q0 + warp * 16 + g;

    const size_t base = (size_t)bh * NT * HP;
    const uint32_t* __restrict__ q16 = g_q16 + base;
    const uint32_t* __restrict__ kh  = g_k16h + base;
    const uint32_t* __restrict__ kl  = g_k16l + base;
    const uint32_t* __restrict__ vth32 = (const uint32_t*)(const void*)g_vt16h
                                         + (size_t)bh * HD * (NT / 2);
    const uint32_t* __restrict__ vtl32 = (const uint32_t*)(const void*)g_vt16l
                                         + (size_t)bh * HD * (NT / 2);

    auto issue = [&](int kt) {
        const uint32_t st = fsm_b + (kt & 1) * (F_STG * 4);
#pragma unroll
        for (int it = 0; it < 2; it++) {
            int c = tid + it * 256;
            int row = c >> 3, pr = (c & 7) * 4;
            uint32_t doff = (row * FP + pr) * 4;
            const size_t ksrc = (size_t)(kt * 64 + row) * HP + pr;
            cp16(st + doff,         kh + ksrc);
            cp16(st + 9216 + doff,  kl + ksrc);
            const size_t vsrc = (size_t)row * (NT / 2) + (size_t)kt * 32 + pr;
            cp16(st + 18432 + doff, vth32 + vsrc);
            cp16(st + 27648 + doff, vtl32 + vsrc);
        }
    };

    uint32_t qa[4][4];
#pragma unroll
    for (int s = 0; s < 4; s++) {
        int o0 = rw * HP + s * 8 + tq;
        int o1 = (rw + 8) * HP + s * 8 + tq;
        qa[s][0] = q16[o0]; qa[s][1] = q16[o1];
        qa[s][2] = q16[o0 + 4]; qa[s][3] = q16[o1 + 4];
    }

    float m_i[2] = {-1e30f, -1e30f}, l_i[2] = {0.f, 0.f};
    float o[8][4] = {};

    const int nkt = 2 * qi + 2;
    issue(0); CP_COMMIT();

    for (int kt = 0; kt < nkt; kt++) {
        if (kt + 1 < nkt) {
            issue(kt + 1); CP_COMMIT();
            CP_WAIT1();
        } else {
            CP_WAIT0();
        }
        __syncthreads();

        if (q0 + warp * 16 + 15 >= kt * 64) {
            uint32_t* st = fsm + (kt & 1) * F_STG;
            const uint32_t* Ksh = st;
            const uint32_t* Ksl = st + 2304;
            const uint32_t* Vth = st + 4608;
            const uint32_t* Vtl = st + 6912;

            float s[8][4];
#pragma unroll
            for (int nt = 0; nt < 8; nt++) {
                float sa[4] = {};
#pragma unroll
                for (int ks = 0; ks < 4; ks++) {
                    int ob = (nt * 8 + g) * FP + ks * 8 + tq;
                    uint32_t bh2[2] = {Ksh[ob], Ksh[ob + 4]};
                    uint32_t bl2[2] = {Ksl[ob], Ksl[ob + 4]};
                    mma_f16(sa, qa[ks], bl2);
                    mma_f16(sa, qa[ks], bh2);
                }
                s[nt][0] = sa[0]; s[nt][1] = sa[1]; s[nt][2] = sa[2]; s[nt][3] = sa[3];
            }

            const bool need_mask = (kt >= 2 * qi);
#pragma unroll
            for (int nt = 0; nt < 8; nt++) {
                int c0 = kt * 64 + nt * 8 + 2 * tq;
#pragma unroll
                for (int r = 0; r < 4; r++) {
                    int col = c0 + (r & 1);
                    int row = rw + (r >> 1) * 8;
                    float v = s[nt][r] * 0.125f;
                    if (need_mask && col > row) v = -1e30f;
                    s[nt][r] = v;
                }
            }

            float sc[2];
#pragma unroll
            for (int r = 0; r < 2; r++) {
                float mx = -1e30f;
#pragma unroll
                for (int nt = 0; nt < 8; nt++)
                    mx = fmaxf(mx, fmaxf(s[nt][2 * r], s[nt][2 * r + 1]));
                mx = fmaxf(mx, __shfl_xor_sync(0xffffffffu, mx, 1));
                mx = fmaxf(mx, __shfl_xor_sync(0xffffffffu, mx, 2));
                float m_new = fmaxf(m_i[r], mx);
                float sum = 0.f;
#pragma unroll
                for (int nt = 0; nt < 8; nt++) {
                    float p0 = __expf(s[nt][2 * r] - m_new);
                    float p1 = __expf(s[nt][2 * r + 1] - m_new);
                    s[nt][2 * r] = p0; s[nt][2 * r + 1] = p1;
                    sum += p0 + p1;
                }
                sum += __shfl_xor_sync(0xffffffffu, sum, 1);
                sum += __shfl_xor_sync(0xffffffffu, sum, 2);
                sc[r]  = __expf(m_i[r] - m_new);
                l_i[r] = l_i[r] * sc[r] + sum;
                m_i[r] = m_new;
            }
#pragma unroll
            for (int nt = 0; nt < 8; nt++) {
                o[nt][0] *= sc[0]; o[nt][1] *= sc[0];
                o[nt][2] *= sc[1]; o[nt][3] *= sc[1];
            }

#pragma unroll
            for (int ks = 0; ks < 4; ks++) {
                uint32_t pa[4] = {
                    pack_f16(s[2 * ks][0],     s[2 * ks][1]),
                    pack_f16(s[2 * ks][2],     s[2 * ks][3]),
                    pack_f16(s[2 * ks + 1][0], s[2 * ks + 1][1]),
                    pack_f16(s[2 * ks + 1][2], s[2 * ks + 1][3])
                };
#pragma unroll
                for (int nt = 0; nt < 8; nt++) {
                    int ob = (nt * 8 + g) * FP + ks * 8 + tq;
                    uint32_t bh2[2] = {Vth[ob], Vth[ob + 4]};
                    uint32_t bl2[2] = {Vtl[ob], Vtl[ob + 4]};
                    mma_f16(o[nt], pa, bl2);
                    mma_f16(o[nt], pa, bh2);
                }
            }
        }

        __syncthreads();
    }

    const int b = bh >> 4, h = bh & 15;
    float inv0 = 1.f / l_i[0], inv1 = 1.f / l_i[1];
#pragma unroll
    for (int nt = 0; nt < 8; nt++) {
        int dp = h * HP + nt * 4 + tq;
        g_y16[(size_t)(b * NT + rw) * (NC / 2) + dp] =
            pack_f16(o[nt][0] * inv0, o[nt][1] * inv0);
        g_y16[(size_t)(b * NT + rw + 8) * (NC / 2) + dp] =
            pack_f16(o[nt][2] * inv1, o[nt][3] * inv1);
    }
}

// ===========================================================================
extern "C" void kernel_launch(void* const* d_in, const int* in_sizes, int n_in,
                              void* d_out, int out_size)
{
    const float* x      = (const float*)d_in[0];
    const float* w_attn = (const float*)d_in[1];
    const float* b_attn = (const float*)d_in[2];
    const float* w_proj = (const float*)d_in[3];
    const float* b_proj = (const float*)d_in[4];
    float* out = (float*)d_out;

    cudaFuncSetAttribute(gemm_f16_kernel<0>,
                         cudaFuncAttributeMaxDynamicSharedMemorySize, G_SMEM_BYTES);
    cudaFuncSetAttribute(gemm_f16_kernel<1>,
                         cudaFuncAttributeMaxDynamicSharedMemorySize, G_SMEM_BYTES);
    cudaFuncSetAttribute(flash_mma_kernel,
                         cudaFuncAttributeMaxDynamicSharedMemorySize, F_SMEM_BYTES);

    // pre-split passes
    {
        uint32_t *x16, *wah, *wal, *wph, *wpl;
        cudaGetSymbolAddress((void**)&x16, g_x16);
        cudaGetSymbolAddress((void**)&wah, g_wa16h);
        cudaGetSymbolAddress((void**)&wal, g_wa16l);
        cudaGetSymbolAddress((void**)&wph, g_wp16h);
        cudaGetSymbolAddress((void**)&wpl, g_wp16l);
        const int npx = NB * NT * NC / 2;
        split_x16_kernel<<<(npx + 255) / 256, 256>>>(x, x16, npx);
        split_wT16_kernel<3 * NC><<<dim3(3 * NC / 64, NC / 32), 256>>>(w_attn, wah, wal);
        split_wT16_kernel<NC><<<dim3(NC / 64, NC / 32), 256>>>(w_proj, wph, wpl);
    }

    dim3 g1(3 * NC / BN, (NB * NT) / BM);   // (24, 64)
    gemm_f16_kernel<0><<<g1, 256, G_SMEM_BYTES>>>(b_attn, nullptr);

    dim3 g2(NT / 128, NB * NHH);            // (16, 64)
    flash_mma_kernel<<<g2, 256, F_SMEM_BYTES>>>();

    dim3 g3(NC / BN, (NB * NT) / BM);       // (8, 64)
    gemm_f16_kernel<1><<<g3, 256, G_SMEM_BYTES>>>(b_proj, out);
}

// round 15
// speedup vs baseline: 2.4636x; 1.5891x over previous
#include <cuda_runtime.h>
#include <cuda_fp16.h>
#include <cstdint>
#include <math.h>

#define NB  4
#define NT  2048
#define NC  1024
#define NHH 16
#define HD  64
#define HP  32   // HD/2 packed u32 per row

// ---------------- device-global scratch (no cudaMalloc allowed) ----------------
// all tensors single fp16 (packed pairs)
__device__ uint32_t g_q16 [(size_t)NB * NHH * NT * HP];
__device__ uint32_t g_k16 [(size_t)NB * NHH * NT * HP];
__device__ uint16_t g_vt16[(size_t)NB * NHH * HD * NT];   // V^T fp16 [b,h][d][t]
__device__ uint32_t g_x16 [(size_t)NB * NT * (NC / 2)];
__device__ uint32_t g_wa16[(size_t)3 * NC * (NC / 2)];    // w_attn^T fp16
__device__ uint32_t g_wp16[(size_t)NC * (NC / 2)];        // w_proj^T fp16
__device__ uint32_t g_y16 [(size_t)NB * NT * (NC / 2)];

// ============================ helpers ============================
__device__ __forceinline__ uint32_t pack_f16(float a, float b) {
    __half2 t = __floats2half2_rn(a, b);
    return *(uint32_t*)&t;
}
__device__ __forceinline__ void mma_f16(float* d, const uint32_t* a, const uint32_t* b) {
    asm volatile(
        "mma.sync.aligned.m16n8k16.row.col.f32.f16.f16.f32 "
        "{%0,%1,%2,%3}, {%4,%5,%6,%7}, {%8,%9}, {%0,%1,%2,%3};"
        : "+f"(d[0]), "+f"(d[1]), "+f"(d[2]), "+f"(d[3])
        : "r"(a[0]), "r"(a[1]), "r"(a[2]), "r"(a[3]), "r"(b[0]), "r"(b[1]));
}
__device__ __forceinline__ uint32_t smem_u32(const void* p) {
    uint32_t a;
    asm("{ .reg .u64 t; cvta.to.shared.u64 t, %1; cvt.u32.u64 %0, t; }"
        : "=r"(a) : "l"(p));
    return a;
}
__device__ __forceinline__ void cp16(uint32_t dst, const void* src) {
    asm volatile("cp.async.cg.shared.global [%0], [%1], 16;" :: "r"(dst), "l"(src));
}
#define CP_COMMIT() asm volatile("cp.async.commit_group;" ::: "memory")
#define CP_WAIT1()  asm volatile("cp.async.wait_group 1;" ::: "memory")
#define CP_WAIT0()  asm volatile("cp.async.wait_group 0;" ::: "memory")

// ===================== pre-convert kernels =====================
__global__ __launch_bounds__(256) void conv_x16_kernel(
    const float* __restrict__ src, uint32_t* __restrict__ d16, int npairs)
{
    int i = blockIdx.x * 256 + threadIdx.x;
    if (i < npairs) {
        float2 v = ((const float2*)src)[i];
        d16[i] = pack_f16(v.x, v.y);
    }
}

// transpose+convert: w [1024][N] fp32 -> [N][512] fp16 packed
template <int N>
__global__ __launch_bounds__(256) void conv_wT16_kernel(
    const float* __restrict__ w, uint32_t* __restrict__ wt)
{
    __shared__ float ws[32][65];
    const int tid = threadIdx.x;
    const int n0 = blockIdx.x * 64, k0 = blockIdx.y * 32;
#pragma unroll
    for (int it = 0; it < 8; it++) {
        int s = tid + it * 256;
        int r = s >> 6, c = s & 63;
        ws[r][c] = w[(size_t)(k0 + r) * N + n0 + c];
    }
    __syncthreads();
#pragma unroll
    for (int it = 0; it < 4; it++) {
        int s = tid + it * 256;
        int n = s >> 4, kp = s & 15;
        wt[(size_t)(n0 + n) * (NC / 2) + (k0 >> 1) + kp] =
            pack_f16(ws[2 * kp][n], ws[2 * kp + 1][n]);
    }
}

// ===================== fp16 single-pass GEMM: 2-stage cp.async, occ 2 =====================
static constexpr int BM = 128, BN = 128, BK = 32;
static constexpr int KTOT = 1024, NCHUNK = KTOT / BK, KP = KTOT / 2;
static constexpr int LDP = 20;
// stage (u32): A 0 | B 2560 ; stage = 5120 u32 = 20KB
static constexpr int G_STG = 5120;
static constexpr int G_SMEM_BYTES = 2 * G_STG * 4;    // 40960

template <int MODE>
__global__ __launch_bounds__(256, 2) void gemm_f16_kernel(
    const float* __restrict__ bias, float* __restrict__ out)
{
    extern __shared__ uint32_t dsm[];
    const uint32_t dsm_b = smem_u32(dsm);

    const int tid  = threadIdx.x;
    const int warp = tid >> 5, lane = tid & 31;
    const int g = lane >> 2, tq = lane & 3;
    const int wm = (warp >> 2) * 64;
    const int wn = (warp & 3) * 32;
    const int m0 = blockIdx.y * BM, n0 = blockIdx.x * BN;

    const uint32_t* __restrict__ Ax = (MODE == 0) ? g_x16 : g_y16;
    const uint32_t* __restrict__ Bx = (MODE == 0) ? g_wa16 : g_wp16;

    const int srow = tid >> 2, sq = (tid & 3) * 4;

    auto issue = [&](int ci) {
        const int kp0 = ci * (BK / 2);
        const uint32_t st = dsm_b + (ci & 1) * (G_STG * 4);
#pragma unroll
        for (int it = 0; it < 2; it++) {
            int row = srow + it * 64;
            uint32_t doff = (row * LDP + sq) * 4;
            cp16(st + doff,         Ax + (size_t)(m0 + row) * KP + kp0 + sq);
            cp16(st + 10240 + doff, Bx + (size_t)(n0 + row) * KP + kp0 + sq);
        }
    };

    float acc[4][4][4] = {};

    issue(0); CP_COMMIT();

    for (int ci = 0; ci < NCHUNK; ci++) {
        if (ci + 1 < NCHUNK) {
            issue(ci + 1); CP_COMMIT();
            CP_WAIT1();
        } else {
            CP_WAIT0();
        }
        __syncthreads();

        const uint32_t* st = dsm + (ci & 1) * G_STG;
        const uint32_t* As = st;
        const uint32_t* Bs = st + 2560;
#pragma unroll
        for (int ks = 0; ks < 2; ks++) {
            const int pb2 = ks * 8 + tq;
            uint32_t ah[4][4];
#pragma unroll
            for (int fm = 0; fm < 4; fm++) {
                int r0 = (wm + fm * 16 + g) * LDP + pb2;
                int r1 = r0 + 8 * LDP;
                ah[fm][0] = As[r0];     ah[fm][1] = As[r1];
                ah[fm][2] = As[r0 + 4]; ah[fm][3] = As[r1 + 4];
            }
            uint32_t bb[4][2];
#pragma unroll
            for (int fn = 0; fn < 4; fn++) {
                int o = (wn + fn * 8 + g) * LDP + pb2;
                bb[fn][0] = Bs[o]; bb[fn][1] = Bs[o + 4];
            }
#pragma unroll
            for (int fm = 0; fm < 4; fm++)
#pragma unroll
                for (int fn = 0; fn < 4; fn++)
                    mma_f16(acc[fm][fn], ah[fm], bb[fn]);
        }

        __syncthreads();
    }

    // ---- epilogue ----
#pragma unroll
    for (int fm = 0; fm < 4; fm++) {
#pragma unroll
        for (int fn = 0; fn < 4; fn++) {
            int ng = n0 + wn + fn * 8 + tq * 2;
#pragma unroll
            for (int half = 0; half < 2; half++) {
                int m = m0 + wm + fm * 16 + g + half * 8;
                float v0 = acc[fm][fn][half * 2 + 0] + bias[ng];
                float v1 = acc[fm][fn][half * 2 + 1] + bias[ng + 1];
                if (MODE == 0) {
                    const int which = ng >> 10;
                    const int h = (ng & (NC - 1)) >> 6;
                    const int d = ng & (HD - 1);
                    const int b = m >> 11, t = m & (NT - 1);
                    if (which == 2) {
                        uint32_t p = pack_f16(v0, v1);
                        size_t vb = ((size_t)(b * NHH + h) * HD + d) * NT + t;
                        g_vt16[vb]      = (uint16_t)(p & 0xffff);
                        g_vt16[vb + NT] = (uint16_t)(p >> 16);
                    } else {
                        size_t idx = (((size_t)b * NHH + h) * NT + t) * HP + (d >> 1);
                        uint32_t* dst = (which == 0) ? g_q16 : g_k16;
                        dst[idx] = pack_f16(v0, v1);
                    }
                } else {
                    *(float2*)(out + (size_t)m * NC + ng) = make_float2(v0, v1);
                }
            }
        }
    }
}

// ===================== flash attention: single-pass fp16, cp.async, occ 2 =====================
static constexpr int FP = 36;
// stage (u32): Ks 0 | Vt 2304 ; stage = 4608 u32 = 18KB
static constexpr int F_STG = 4608;
static constexpr int F_SMEM_BYTES = 2 * F_STG * 4;    // 36864

__global__ __launch_bounds__(256, 2) void flash_mma_kernel()
{
    extern __shared__ uint32_t fsm[];
    const uint32_t fsm_b = smem_u32(fsm);

    const int tid  = threadIdx.x;
    const int warp = tid >> 5, lane = tid & 31;
    const int g = lane >> 2, tq = lane & 3;
    const int qi = blockIdx.x, bh = blockIdx.y;
    const int q0 = qi * 128;
    const int rw = q0 + warp * 16 + g;

    const size_t base = (size_t)bh * NT * HP;
    const uint32_t* __restrict__ q16 = g_q16 + base;
    const uint32_t* __restrict__ k16 = g_k16 + base;
    const uint32_t* __restrict__ vt32 = (const uint32_t*)(const void*)g_vt16
                                        + (size_t)bh * HD * (NT / 2);

    auto issue = [&](int kt) {
        const uint32_t st = fsm_b + (kt & 1) * (F_STG * 4);
#pragma unroll
        for (int it = 0; it < 2; it++) {
            int c = tid + it * 256;
            int row = c >> 3, pr = (c & 7) * 4;
            uint32_t doff = (row * FP + pr) * 4;
            cp16(st + doff,        k16 + (size_t)(kt * 64 + row) * HP + pr);
            cp16(st + 9216 + doff, vt32 + (size_t)row * (NT / 2) + (size_t)kt * 32 + pr);
        }
    };

    // Q fragments (rows rw, rw+8; full HD)
    uint32_t qa[4][4];
#pragma unroll
    for (int s = 0; s < 4; s++) {
        int o0 = rw * HP + s * 8 + tq;
        int o1 = (rw + 8) * HP + s * 8 + tq;
        qa[s][0] = q16[o0]; qa[s][1] = q16[o1];
        qa[s][2] = q16[o0 + 4]; qa[s][3] = q16[o1 + 4];
    }

    float m_i[2] = {-1e30f, -1e30f}, l_i[2] = {0.f, 0.f};
    float o[8][4] = {};

    const int nkt = 2 * qi + 2;
    issue(0); CP_COMMIT();

    for (int kt = 0; kt < nkt; kt++) {
        if (kt + 1 < nkt) {
            issue(kt + 1); CP_COMMIT();
            CP_WAIT1();
        } else {
            CP_WAIT0();
        }
        __syncthreads();

        if (q0 + warp * 16 + 15 >= kt * 64) {
            uint32_t* st = fsm + (kt & 1) * F_STG;
            const uint32_t* Ks = st;
            const uint32_t* Vt = st + 2304;

            // ---- S = Q K^T (single pass) ----
            float s[8][4];
#pragma unroll
            for (int nt = 0; nt < 8; nt++) {
                float sa[4] = {};
#pragma unroll
                for (int ks = 0; ks < 4; ks++) {
                    int ob = (nt * 8 + g) * FP + ks * 8 + tq;
                    uint32_t b2[2] = {Ks[ob], Ks[ob + 4]};
                    mma_f16(sa, qa[ks], b2);
                }
                s[nt][0] = sa[0]; s[nt][1] = sa[1]; s[nt][2] = sa[2]; s[nt][3] = sa[3];
            }

            const bool need_mask = (kt >= 2 * qi);
#pragma unroll
            for (int nt = 0; nt < 8; nt++) {
                int c0 = kt * 64 + nt * 8 + 2 * tq;
#pragma unroll
                for (int r = 0; r < 4; r++) {
                    int col = c0 + (r & 1);
                    int row = rw + (r >> 1) * 8;
                    float v = s[nt][r] * 0.125f;
                    if (need_mask && col > row) v = -1e30f;
                    s[nt][r] = v;
                }
            }

            float sc[2];
#pragma unroll
            for (int r = 0; r < 2; r++) {
                float mx = -1e30f;
#pragma unroll
                for (int nt = 0; nt < 8; nt++)
                    mx = fmaxf(mx, fmaxf(s[nt][2 * r], s[nt][2 * r + 1]));
                mx = fmaxf(mx, __shfl_xor_sync(0xffffffffu, mx, 1));
                mx = fmaxf(mx, __shfl_xor_sync(0xffffffffu, mx, 2));
                float m_new = fmaxf(m_i[r], mx);
                float sum = 0.f;
#pragma unroll
                for (int nt = 0; nt < 8; nt++) {
                    float p0 = __expf(s[nt][2 * r] - m_new);
                    float p1 = __expf(s[nt][2 * r + 1] - m_new);
                    s[nt][2 * r] = p0; s[nt][2 * r + 1] = p1;
                    sum += p0 + p1;
                }
                sum += __shfl_xor_sync(0xffffffffu, sum, 1);
                sum += __shfl_xor_sync(0xffffffffu, sum, 2);
                sc[r]  = __expf(m_i[r] - m_new);
                l_i[r] = l_i[r] * sc[r] + sum;
                m_i[r] = m_new;
            }
#pragma unroll
            for (int nt = 0; nt < 8; nt++) {
                o[nt][0] *= sc[0]; o[nt][1] *= sc[0];
                o[nt][2] *= sc[1]; o[nt][3] *= sc[1];
            }

            // ---- PV (single pass) ----
#pragma unroll
            for (int ks = 0; ks < 4; ks++) {
                uint32_t pa[4] = {
                    pack_f16(s[2 * ks][0],     s[2 * ks][1]),
                    pack_f16(s[2 * ks][2],     s[2 * ks][3]),
                    pack_f16(s[2 * ks + 1][0], s[2 * ks + 1][1]),
                    pack_f16(s[2 * ks + 1][2], s[2 * ks + 1][3])
                };
#pragma unroll
                for (int nt = 0; nt < 8; nt++) {
                    int ob = (nt * 8 + g) * FP + ks * 8 + tq;
                    uint32_t b2[2] = {Vt[ob], Vt[ob + 4]};
                    mma_f16(o[nt], pa, b2);
                }
            }
        }

        __syncthreads();
    }

    // ---- epilogue: y fp16x2 ----
    const int b = bh >> 4, h = bh & 15;
    float inv0 = 1.f / l_i[0], inv1 = 1.f / l_i[1];
#pragma unroll
    for (int nt = 0; nt < 8; nt++) {
        int dp = h * HP + nt * 4 + tq;
        g_y16[(size_t)(b * NT + rw) * (NC / 2) + dp] =
            pack_f16(o[nt][0] * inv0, o[nt][1] * inv0);
        g_y16[(size_t)(b * NT + rw + 8) * (NC / 2) + dp] =
            pack_f16(o[nt][2] * inv1, o[nt][3] * inv1);
    }
}

// ===========================================================================
extern "C" void kernel_launch(void* const* d_in, const int* in_sizes, int n_in,
                              void* d_out, int out_size)
{
    const float* x      = (const float*)d_in[0];
    const float* w_attn = (const float*)d_in[1];
    const float* b_attn = (const float*)d_in[2];
    const float* w_proj = (const float*)d_in[3];
    const float* b_proj = (const float*)d_in[4];
    float* out = (float*)d_out;

    cudaFuncSetAttribute(gemm_f16_kernel<0>,
                         cudaFuncAttributeMaxDynamicSharedMemorySize, G_SMEM_BYTES);
    cudaFuncSetAttribute(gemm_f16_kernel<1>,
                         cudaFuncAttributeMaxDynamicSharedMemorySize, G_SMEM_BYTES);
    cudaFuncSetAttribute(flash_mma_kernel,
                         cudaFuncAttributeMaxDynamicSharedMemorySize, F_SMEM_BYTES);

    // pre-convert passes
    {
        uint32_t *x16, *wa, *wp;
        cudaGetSymbolAddress((void**)&x16, g_x16);
        cudaGetSymbolAddress((void**)&wa,  g_wa16);
        cudaGetSymbolAddress((void**)&wp,  g_wp16);
        const int npx = NB * NT * NC / 2;
        conv_x16_kernel<<<(npx + 255) / 256, 256>>>(x, x16, npx);
        conv_wT16_kernel<3 * NC><<<dim3(3 * NC / 64, NC / 32), 256>>>(w_attn, wa);
        conv_wT16_kernel<NC><<<dim3(NC / 64, NC / 32), 256>>>(w_proj, wp);
    }

    dim3 g1(3 * NC / BN, (NB * NT) / BM);   // (24, 64)
    gemm_f16_kernel<0><<<g1, 256, G_SMEM_BYTES>>>(b_attn, nullptr);

    dim3 g2(NT / 128, NB * NHH);            // (16, 64)
    flash_mma_kernel<<<g2, 256, F_SMEM_BYTES>>>();

    dim3 g3(NC / BN, (NB * NT) / BM);       // (8, 64)
    gemm_f16_kernel<1><<<g3, 256, G_SMEM_BYTES>>>(b_proj, out);
}

// round 16
// speedup vs baseline: 2.6342x; 1.0692x over previous
#include <cuda_runtime.h>
#include <cuda_fp16.h>
#include <cstdint>
#include <math.h>

#define NB  4
#define NT  2048
#define NC  1024
#define NHH 16
#define HD  64
#define HP  32   // HD/2 packed u32 per row

// ---------------- device-global scratch (no cudaMalloc allowed) ----------------
__device__ uint32_t g_q16 [(size_t)NB * NHH * NT * HP];
__device__ uint32_t g_k16 [(size_t)NB * NHH * NT * HP];
__device__ uint16_t g_vt16[(size_t)NB * NHH * HD * NT];   // V^T fp16 [b,h][d][t]
__device__ uint32_t g_x16 [(size_t)NB * NT * (NC / 2)];
__device__ uint32_t g_wa16[(size_t)3 * NC * (NC / 2)];    // w_attn^T fp16
__device__ uint32_t g_wp16[(size_t)NC * (NC / 2)];        // w_proj^T fp16
__device__ uint32_t g_y16 [(size_t)NB * NT * (NC / 2)];

// ============================ helpers ============================
__device__ __forceinline__ uint32_t pack_f16(float a, float b) {
    __half2 t = __floats2half2_rn(a, b);
    return *(uint32_t*)&t;
}
__device__ __forceinline__ void mma_f16(float* d, const uint32_t* a, const uint32_t* b) {
    asm volatile(
        "mma.sync.aligned.m16n8k16.row.col.f32.f16.f16.f32 "
        "{%0,%1,%2,%3}, {%4,%5,%6,%7}, {%8,%9}, {%0,%1,%2,%3};"
        : "+f"(d[0]), "+f"(d[1]), "+f"(d[2]), "+f"(d[3])
        : "r"(a[0]), "r"(a[1]), "r"(a[2]), "r"(a[3]), "r"(b[0]), "r"(b[1]));
}
__device__ __forceinline__ uint32_t smem_u32(const void* p) {
    uint32_t a;
    asm("{ .reg .u64 t; cvta.to.shared.u64 t, %1; cvt.u32.u64 %0, t; }"
        : "=r"(a) : "l"(p));
    return a;
}
__device__ __forceinline__ void cp16(uint32_t dst, const void* src) {
    asm volatile("cp.async.cg.shared.global [%0], [%1], 16;" :: "r"(dst), "l"(src));
}
#define CP_COMMIT() asm volatile("cp.async.commit_group;" ::: "memory")
#define CP_WAIT1()  asm volatile("cp.async.wait_group 1;" ::: "memory")
#define CP_WAIT0()  asm volatile("cp.async.wait_group 0;" ::: "memory")

// ===================== pre-convert kernels (vectorized) =====================
__global__ __launch_bounds__(256) void conv_x16_kernel(
    const float4* __restrict__ src, uint2* __restrict__ d16, int nquads)
{
    int i = blockIdx.x * 256 + threadIdx.x;
    if (i < nquads) {
        float4 v = src[i];
        d16[i] = make_uint2(pack_f16(v.x, v.y), pack_f16(v.z, v.w));
    }
}

// transpose+convert: w [1024][N] fp32 -> [N][512] fp16 packed
template <int N>
__global__ __launch_bounds__(256) void conv_wT16_kernel(
    const float* __restrict__ w, uint32_t* __restrict__ wt)
{
    __shared__ float ws[32][65];
    const int tid = threadIdx.x;
    const int n0 = blockIdx.x * 64, k0 = blockIdx.y * 32;
#pragma unroll
    for (int it = 0; it < 8; it++) {
        int s = tid + it * 256;
        int r = s >> 6, c = s & 63;
        ws[r][c] = w[(size_t)(k0 + r) * N + n0 + c];
    }
    __syncthreads();
#pragma unroll
    for (int it = 0; it < 4; it++) {
        int s = tid + it * 256;
        int n = s >> 4, kp = s & 15;
        wt[(size_t)(n0 + n) * (NC / 2) + (k0 >> 1) + kp] =
            pack_f16(ws[2 * kp][n], ws[2 * kp + 1][n]);
    }
}

// ===================== fp16 GEMM: 3-stage cp.async, 1 barrier/chunk, occ 2 =====================
static constexpr int BM = 128, BN = 128, BK = 32;
static constexpr int KTOT = 1024, NCHUNK = KTOT / BK, KP = KTOT / 2;
static constexpr int LDP = 20;
static constexpr int G_STG = 5120;                    // u32 per stage (20KB)
static constexpr int G_SMEM_BYTES = 3 * G_STG * 4;    // 61440 -> 2 CTAs/SM

template <int MODE>
__global__ __launch_bounds__(256, 2) void gemm_f16_kernel(
    const float* __restrict__ bias, float* __restrict__ out)
{
    extern __shared__ uint32_t dsm[];
    const uint32_t dsm_b = smem_u32(dsm);

    const int tid  = threadIdx.x;
    const int warp = tid >> 5, lane = tid & 31;
    const int g = lane >> 2, tq = lane & 3;
    const int wm = (warp >> 2) * 64;
    const int wn = (warp & 3) * 32;
    const int m0 = blockIdx.y * BM, n0 = blockIdx.x * BN;

    const uint32_t* __restrict__ Ax = (MODE == 0) ? g_x16 : g_y16;
    const uint32_t* __restrict__ Bx = (MODE == 0) ? g_wa16 : g_wp16;

    const int srow = tid >> 2, sq = (tid & 3) * 4;

    auto issue = [&](int ci) {
        const int kp0 = ci * (BK / 2);
        const uint32_t st = dsm_b + (ci % 3) * (G_STG * 4);
#pragma unroll
        for (int it = 0; it < 2; it++) {
            int row = srow + it * 64;
            uint32_t doff = (row * LDP + sq) * 4;
            cp16(st + doff,         Ax + (size_t)(m0 + row) * KP + kp0 + sq);
            cp16(st + 10240 + doff, Bx + (size_t)(n0 + row) * KP + kp0 + sq);
        }
    };

    float acc[4][4][4] = {};

    issue(0); CP_COMMIT();
    issue(1); CP_COMMIT();

    for (int ci = 0; ci < NCHUNK; ci++) {
        if (ci + 1 < NCHUNK) CP_WAIT1(); else CP_WAIT0();
        __syncthreads();

        const uint32_t* st = dsm + (ci % 3) * G_STG;
        const uint32_t* As = st;
        const uint32_t* Bs = st + 2560;
#pragma unroll
        for (int ks = 0; ks < 2; ks++) {
            const int pb2 = ks * 8 + tq;
            uint32_t ah[4][4];
#pragma unroll
            for (int fm = 0; fm < 4; fm++) {
                int r0 = (wm + fm * 16 + g) * LDP + pb2;
                int r1 = r0 + 8 * LDP;
                ah[fm][0] = As[r0];     ah[fm][1] = As[r1];
                ah[fm][2] = As[r0 + 4]; ah[fm][3] = As[r1 + 4];
            }
            uint32_t bb[4][2];
#pragma unroll
            for (int fn = 0; fn < 4; fn++) {
                int o = (wn + fn * 8 + g) * LDP + pb2;
                bb[fn][0] = Bs[o]; bb[fn][1] = Bs[o + 4];
            }
#pragma unroll
            for (int fm = 0; fm < 4; fm++)
#pragma unroll
                for (int fn = 0; fn < 4; fn++)
                    mma_f16(acc[fm][fn], ah[fm], bb[fn]);
        }

        if (ci + 2 < NCHUNK) issue(ci + 2);
        CP_COMMIT();
    }

    // ---- epilogue ----
#pragma unroll
    for (int fm = 0; fm < 4; fm++) {
#pragma unroll
        for (int fn = 0; fn < 4; fn++) {
            int ng = n0 + wn + fn * 8 + tq * 2;
#pragma unroll
            for (int half = 0; half < 2; half++) {
                int m = m0 + wm + fm * 16 + g + half * 8;
                float v0 = acc[fm][fn][half * 2 + 0] + bias[ng];
                float v1 = acc[fm][fn][half * 2 + 1] + bias[ng + 1];
                if (MODE == 0) {
                    const int which = ng >> 10;
                    const int h = (ng & (NC - 1)) >> 6;
                    const int d = ng & (HD - 1);
                    const int b = m >> 11, t = m & (NT - 1);
                    if (which == 2) {
                        uint32_t p = pack_f16(v0, v1);
                        size_t vb = ((size_t)(b * NHH + h) * HD + d) * NT + t;
                        g_vt16[vb]      = (uint16_t)(p & 0xffff);
                        g_vt16[vb + NT] = (uint16_t)(p >> 16);
                    } else {
                        size_t idx = (((size_t)b * NHH + h) * NT + t) * HP + (d >> 1);
                        uint32_t* dst = (which == 0) ? g_q16 : g_k16;
                        dst[idx] = pack_f16(v0, v1);
                    }
                } else {
                    *(float2*)(out + (size_t)m * NC + ng) = make_float2(v0, v1);
                }
            }
        }
    }
}

// ===================== flash attention: 3-stage cp.async, 1 barrier/tile, occ 2 =====================
static constexpr int FP = 36;
static constexpr int F_STG = 4608;                    // u32 per stage (18KB)
static constexpr int F_SMEM_BYTES = 3 * F_STG * 4;    // 55296 -> 2 CTAs/SM

__global__ __launch_bounds__(256, 2) void flash_mma_kernel()
{
    extern __shared__ uint32_t fsm[];
    const uint32_t fsm_b = smem_u32(fsm);

    const int tid  = threadIdx.x;
    const int warp = tid >> 5, lane = tid & 31;
    const int g = lane >> 2, tq = lane & 3;
    const int qi = blockIdx.x, bh = blockIdx.y;
    const int q0 = qi * 128;
    const int rw = q0 + warp * 16 + g;

    const size_t base = (size_t)bh * NT * HP;
    const uint32_t* __restrict__ q16 = g_q16 + base;
    const uint32_t* __restrict__ k16 = g_k16 + base;
    const uint32_t* __restrict__ vt32 = (const uint32_t*)(const void*)g_vt16
                                        + (size_t)bh * HD * (NT / 2);

    auto issue = [&](int kt) {
        const uint32_t st = fsm_b + (kt % 3) * (F_STG * 4);
#pragma unroll
        for (int it = 0; it < 2; it++) {
            int c = tid + it * 256;
            int row = c >> 3, pr = (c & 7) * 4;
            uint32_t doff = (row * FP + pr) * 4;
            cp16(st + doff,        k16 + (size_t)(kt * 64 + row) * HP + pr);
            cp16(st + 9216 + doff, vt32 + (size_t)row * (NT / 2) + (size_t)kt * 32 + pr);
        }
    };

    // Q fragments (rows rw, rw+8; full HD)
    uint32_t qa[4][4];
#pragma unroll
    for (int s = 0; s < 4; s++) {
        int o0 = rw * HP + s * 8 + tq;
        int o1 = (rw + 8) * HP + s * 8 + tq;
        qa[s][0] = q16[o0]; qa[s][1] = q16[o1];
        qa[s][2] = q16[o0 + 4]; qa[s][3] = q16[o1 + 4];
    }

    float m_i[2] = {-1e30f, -1e30f}, l_i[2] = {0.f, 0.f};
    float o[8][4] = {};

    const int nkt = 2 * qi + 2;
    issue(0); CP_COMMIT();
    if (nkt > 1) { issue(1); } CP_COMMIT();

    for (int kt = 0; kt < nkt; kt++) {
        if (kt + 1 < nkt) CP_WAIT1(); else CP_WAIT0();
        __syncthreads();

        if (q0 + warp * 16 + 15 >= kt * 64) {
            uint32_t* st = fsm + (kt % 3) * F_STG;
            const uint32_t* Ks = st;
            const uint32_t* Vt = st + 2304;

            // ---- S = Q K^T ----
            float s[8][4];
#pragma unroll
            for (int nt = 0; nt < 8; nt++) {
                float sa[4] = {};
#pragma unroll
                for (int ks = 0; ks < 4; ks++) {
                    int ob = (nt * 8 + g) * FP + ks * 8 + tq;
                    uint32_t b2[2] = {Ks[ob], Ks[ob + 4]};
                    mma_f16(sa, qa[ks], b2);
                }
                s[nt][0] = sa[0]; s[nt][1] = sa[1]; s[nt][2] = sa[2]; s[nt][3] = sa[3];
            }

            const bool need_mask = (kt >= 2 * qi);
#pragma unroll
            for (int nt = 0; nt < 8; nt++) {
                int c0 = kt * 64 + nt * 8 + 2 * tq;
#pragma unroll
                for (int r = 0; r < 4; r++) {
                    int col = c0 + (r & 1);
                    int row = rw + (r >> 1) * 8;
                    float v = s[nt][r] * 0.125f;
                    if (need_mask && col > row) v = -1e30f;
                    s[nt][r] = v;
                }
            }

            float sc[2];
#pragma unroll
            for (int r = 0; r < 2; r++) {
                float mx = -1e30f;
#pragma unroll
                for (int nt = 0; nt < 8; nt++)
                    mx = fmaxf(mx, fmaxf(s[nt][2 * r], s[nt][2 * r + 1]));
                mx = fmaxf(mx, __shfl_xor_sync(0xffffffffu, mx, 1));
                mx = fmaxf(mx, __shfl_xor_sync(0xffffffffu, mx, 2));
                float m_new = fmaxf(m_i[r], mx);
                float sum = 0.f;
#pragma unroll
                for (int nt = 0; nt < 8; nt++) {
                    float p0 = __expf(s[nt][2 * r] - m_new);
                    float p1 = __expf(s[nt][2 * r + 1] - m_new);
                    s[nt][2 * r] = p0; s[nt][2 * r + 1] = p1;
                    sum += p0 + p1;
                }
                sum += __shfl_xor_sync(0xffffffffu, sum, 1);
                sum += __shfl_xor_sync(0xffffffffu, sum, 2);
                sc[r]  = __expf(m_i[r] - m_new);
                l_i[r] = l_i[r] * sc[r] + sum;
                m_i[r] = m_new;
            }
#pragma unroll
            for (int nt = 0; nt < 8; nt++) {
                o[nt][0] *= sc[0]; o[nt][1] *= sc[0];
                o[nt][2] *= sc[1]; o[nt][3] *= sc[1];
            }

            // ---- PV ----
#pragma unroll
            for (int ks = 0; ks < 4; ks++) {
                uint32_t pa[4] = {
                    pack_f16(s[2 * ks][0],     s[2 * ks][1]),
                    pack_f16(s[2 * ks][2],     s[2 * ks][3]),
                    pack_f16(s[2 * ks + 1][0], s[2 * ks + 1][1]),
                    pack_f16(s[2 * ks + 1][2], s[2 * ks + 1][3])
                };
#pragma unroll
                for (int nt = 0; nt < 8; nt++) {
                    int ob = (nt * 8 + g) * FP + ks * 8 + tq;
                    uint32_t b2[2] = {Vt[ob], Vt[ob + 4]};
                    mma_f16(o[nt], pa, b2);
                }
            }
        }

        if (kt + 2 < nkt) issue(kt + 2);
        CP_COMMIT();
    }

    // ---- epilogue: y fp16x2 ----
    const int b = bh >> 4, h = bh & 15;
    float inv0 = 1.f / l_i[0], inv1 = 1.f / l_i[1];
#pragma unroll
    for (int nt = 0; nt < 8; nt++) {
        int dp = h * HP + nt * 4 + tq;
        g_y16[(size_t)(b * NT + rw) * (NC / 2) + dp] =
            pack_f16(o[nt][0] * inv0, o[nt][1] * inv0);
        g_y16[(size_t)(b * NT + rw + 8) * (NC / 2) + dp] =
            pack_f16(o[nt][2] * inv1, o[nt][3] * inv1);
    }
}

// ===========================================================================
extern "C" void kernel_launch(void* const* d_in, const int* in_sizes, int n_in,
                              void* d_out, int out_size)
{
    const float* x      = (const float*)d_in[0];
    const float* w_attn = (const float*)d_in[1];
    const float* b_attn = (const float*)d_in[2];
    const float* w_proj = (const float*)d_in[3];
    const float* b_proj = (const float*)d_in[4];
    float* out = (float*)d_out;

    cudaFuncSetAttribute(gemm_f16_kernel<0>,
                         cudaFuncAttributeMaxDynamicSharedMemorySize, G_SMEM_BYTES);
    cudaFuncSetAttribute(gemm_f16_kernel<1>,
                         cudaFuncAttributeMaxDynamicSharedMemorySize, G_SMEM_BYTES);
    cudaFuncSetAttribute(flash_mma_kernel,
                         cudaFuncAttributeMaxDynamicSharedMemorySize, F_SMEM_BYTES);

    // pre-convert passes
    {
        uint32_t *x16, *wa, *wp;
        cudaGetSymbolAddress((void**)&x16, g_x16);
        cudaGetSymbolAddress((void**)&wa,  g_wa16);
        cudaGetSymbolAddress((void**)&wp,  g_wp16);
        const int nq = NB * NT * NC / 4;
        conv_x16_kernel<<<(nq + 255) / 256, 256>>>((const float4*)x, (uint2*)x16, nq);
        conv_wT16_kernel<3 * NC><<<dim3(3 * NC / 64, NC / 32), 256>>>(w_attn, wa);
        conv_wT16_kernel<NC><<<dim3(NC / 64, NC / 32), 256>>>(w_proj, wp);
    }

    dim3 g1(3 * NC / BN, (NB * NT) / BM);   // (24, 64)
    gemm_f16_kernel<0><<<g1, 256, G_SMEM_BYTES>>>(b_attn, nullptr);

    dim3 g2(NT / 128, NB * NHH);            // (16, 64)
    flash_mma_kernel<<<g2, 256, F_SMEM_BYTES>>>();

    dim3 g3(NC / BN, (NB * NT) / BM);       // (8, 64)
    gemm_f16_kernel<1><<<g3, 256, G_SMEM_BYTES>>>(b_proj, out);
}